// round 14
// baseline (speedup 1.0000x reference)
#include <cuda_runtime.h>
#include <math.h>
#include <stdint.h>

// Problem shape (fixed): x [8, 128, 512, 512] f32, conv_w [16,1,3,3], conv_b [16]
// out [8, 1, 512, 512] f32 with per-tile reassembly layout:
//   out_flat = b*HW + seg*16384 + r*128 + c, seg = ti*4 + tj
#define Bb   8
#define Cc   128
#define Hh   512
#define Ww   512
#define HW   (Hh * Ww)        /* 262144 */
#define CHW  (Cc * HW)
#define TS   128              /* tile side */
#define NSEG 16

__device__ __forceinline__ uint32_t smem_u32(const void* p) {
    return (uint32_t)__cvta_generic_to_shared(p);
}

__device__ __forceinline__ void mbar_init(uint32_t a, int cnt) {
    asm volatile("mbarrier.init.shared.b64 [%0], %1;" :: "r"(a), "r"(cnt) : "memory");
}

__device__ __forceinline__ void mbar_arrive(uint32_t a) {
    // release.cta: orders the preceding STS before waiters' acquire
    asm volatile("mbarrier.arrive.release.cta.shared::cta.b64 _, [%0];" :: "r"(a) : "memory");
}

__device__ __forceinline__ void mbar_wait_p0(uint32_t a) {
    uint32_t done = 0;
    while (!done) {
        asm volatile(
            "{\n\t.reg .pred p;\n\t"
            "mbarrier.try_wait.parity.acquire.cta.shared::cta.b64 p, [%1], 0;\n\t"
            "selp.b32 %0, 1, 0, p;\n\t}"
            : "=r"(done) : "r"(a) : "memory");
    }
}

// Fully fused kernel: 16-row strips + per-row mbarrier dataflow + streaming
// stores + smem-resident conv weights.
// One block = one 16-row x 128-col strip of one (batch, segment) tile.
// 18 warps: warp w computes the channel-L2 of smem row w (16 rows + 2 halo;
// lane = float4 col group -> 512B contiguous per warp per channel; single
// uninterrupted 128-channel load stream), STS, arrive mbar[w]. Conv warp w
// (w<16) waits only on mbar[w..w+2], then 3x3 conv (zero pad at tile edges)
// + bias + sigmoid, one float4 output group per lane, __stwt store.
__global__ void __launch_bounds__(576) fused_kernel(const float* __restrict__ x,
                                                    const float* __restrict__ conv_w,
                                                    const float* __restrict__ conv_b,
                                                    float* __restrict__ out) {
    __shared__ float s[18][128];
    __shared__ __align__(8) unsigned long long mbar[18];
    __shared__ float swb[10];     // 9 weights + bias for this block's segment

    int bid   = blockIdx.x;
    int strip = bid & 7;          // 8 strips of 16 rows per tile
    int seg   = (bid >> 3) & 15;
    int b     = bid >> 7;
    int ti    = seg >> 2;
    int tj    = seg & 3;
    int r0    = strip * 16;
    int tid   = threadIdx.x;

    int row = tid >> 5;           // warp 0..17 = smem row (warp-uniform)
    int l   = tid & 31;           // lane = float4 column group
    int gr  = r0 - 1 + row;       // row within tile (-1 .. 128)

    // ---- init: per-row mbarriers + weights/bias into smem ----
    if (tid < 18) mbar_init(smem_u32(&mbar[tid]), 1);
    if (tid >= 32 && tid < 41) swb[tid - 32] = __ldg(conv_w + seg * 9 + (tid - 32));
    if (tid == 41)             swb[9]        = __ldg(conv_b + seg);
    __syncthreads();

    // ---- Phase 1: channel-L2 into smem (uninterrupted load stream) ----
    float ax = 0.f, ay = 0.f, az = 0.f, aw = 0.f;
    if ((unsigned)gr < (unsigned)TS) {
        const float4* xp = reinterpret_cast<const float4*>(
            x + (size_t)b * CHW + (size_t)(ti * TS + gr) * Ww + tj * TS) + l;
        #pragma unroll 32
        for (int c = 0; c < Cc; ++c) {
            float4 v = __ldg(xp + (size_t)c * (HW / 4));
            ax = fmaf(v.x, v.x, ax);
            ay = fmaf(v.y, v.y, ay);
            az = fmaf(v.z, v.z, az);
            aw = fmaf(v.w, v.w, aw);
        }
    }
    float4 r;
    r.x = sqrtf(ax);
    r.y = sqrtf(ay);
    r.z = sqrtf(az);
    r.w = sqrtf(aw);
    *reinterpret_cast<float4*>(&s[row][l * 4]) = r;    // zeros for out-of-tile halo rows
    __syncwarp();
    if (l == 0) mbar_arrive(smem_u32(&mbar[row]));     // row ready

    // ---- Phase 2: conv + sigmoid; warp w handles output row w (w < 16) ----
    if (row < 16) {
        // Wait only for the 3 rows this warp consumes
        mbar_wait_p0(smem_u32(&mbar[row]));
        mbar_wait_p0(smem_u32(&mbar[row + 1]));
        mbar_wait_p0(smem_u32(&mbar[row + 2]));

        // Weights + bias from smem (LDS broadcast, warp-uniform)
        float wt[9];
        #pragma unroll
        for (int k = 0; k < 9; ++k) wt[k] = swb[k];
        float bias = swb[9];

        int cq = l * 4;           // output col of first element

        float a0 = 0.f, a1 = 0.f, a2 = 0.f, a3 = 0.f;
        #pragma unroll
        for (int dr = 0; dr < 3; ++dr) {
            const float* sr = s[row + dr];
            float4 vc = *reinterpret_cast<const float4*>(&sr[cq]);
            float vm1 = (cq == 0)   ? 0.f : sr[cq - 1];
            float vp4 = (cq == 124) ? 0.f : sr[cq + 4];
            float w0 = wt[dr * 3], w1 = wt[dr * 3 + 1], w2 = wt[dr * 3 + 2];
            a0 = fmaf(w0, vm1,  fmaf(w1, vc.x, fmaf(w2, vc.y, a0)));
            a1 = fmaf(w0, vc.x, fmaf(w1, vc.y, fmaf(w2, vc.z, a1)));
            a2 = fmaf(w0, vc.y, fmaf(w1, vc.z, fmaf(w2, vc.w, a2)));
            a3 = fmaf(w0, vc.z, fmaf(w1, vc.w, fmaf(w2, vp4,  a3)));
        }

        float4 o;
        o.x = 1.f / (1.f + __expf(-(a0 + bias)));
        o.y = 1.f / (1.f + __expf(-(a1 + bias)));
        o.z = 1.f / (1.f + __expf(-(a2 + bias)));
        o.w = 1.f / (1.f + __expf(-(a3 + bias)));

        size_t oofs = (size_t)b * HW + (size_t)seg * (TS * TS)
                    + (size_t)(r0 + row) * TS + cq;
        __stwt(reinterpret_cast<float4*>(out + oofs), o);   // streaming store
    }
}

extern "C" void kernel_launch(void* const* d_in, const int* in_sizes, int n_in,
                              void* d_out, int out_size) {
    const float* x  = (const float*)d_in[0];
    const float* cw = (const float*)d_in[1];
    const float* cb = (const float*)d_in[2];
    float* out = (float*)d_out;

    // 8 strips x 16 segs x 8 batches = 1024 blocks, 576 threads each
    fused_kernel<<<Bb * NSEG * 8, 576>>>(x, cw, cb, out);
}

// round 15
// speedup vs baseline: 1.0282x; 1.0282x over previous
#include <cuda_runtime.h>
#include <math.h>
#include <stdint.h>

// Problem shape (fixed): x [8, 128, 512, 512] f32, conv_w [16,1,3,3], conv_b [16]
// out [8, 1, 512, 512] f32 with per-tile reassembly layout:
//   out_flat = b*HW + seg*16384 + r*128 + c, seg = ti*4 + tj
#define Bb   8
#define Cc   128
#define Hh   512
#define Ww   512
#define HW   (Hh * Ww)        /* 262144 */
#define CHW  (Cc * HW)
#define TS   128              /* tile side */
#define NSEG 16

__device__ __forceinline__ uint32_t smem_u32(const void* p) {
    return (uint32_t)__cvta_generic_to_shared(p);
}

__device__ __forceinline__ void mbar_init(uint32_t a, int cnt) {
    asm volatile("mbarrier.init.shared.b64 [%0], %1;" :: "r"(a), "r"(cnt) : "memory");
}

__device__ __forceinline__ void mbar_arrive(uint32_t a) {
    // release.cta: orders the preceding STS before waiters' acquire
    asm volatile("mbarrier.arrive.release.cta.shared::cta.b64 _, [%0];" :: "r"(a) : "memory");
}

__device__ __forceinline__ void mbar_wait_p0(uint32_t a) {
    uint32_t done = 0;
    while (!done) {
        asm volatile(
            "{\n\t.reg .pred p;\n\t"
            "mbarrier.try_wait.parity.acquire.cta.shared::cta.b64 p, [%1], 0;\n\t"
            "selp.b32 %0, 1, 0, p;\n\t}"
            : "=r"(done) : "r"(a) : "memory");
    }
}

// Fully fused kernel (best measured configuration, R12):
// 16-row strips + per-row mbarrier dataflow + streaming stores.
// One block = one 16-row x 128-col strip of one (batch, segment) tile.
// 18 warps: warp w computes the channel-L2 of smem row w (16 rows + 2 halo;
// lane = float4 col group -> 512B contiguous per warp per channel; single
// uninterrupted 128-channel load stream, unroll 16), STS, arrive mbar[w].
// Conv warp w (w<16) waits only on mbar[w..w+2], then 3x3 conv (zero pad at
// tile edges) + bias + sigmoid, one float4 output group per lane, __stwt.
__global__ void __launch_bounds__(576) fused_kernel(const float* __restrict__ x,
                                                    const float* __restrict__ conv_w,
                                                    const float* __restrict__ conv_b,
                                                    float* __restrict__ out) {
    __shared__ float s[18][128];
    __shared__ __align__(8) unsigned long long mbar[18];

    int bid   = blockIdx.x;
    int strip = bid & 7;          // 8 strips of 16 rows per tile
    int seg   = (bid >> 3) & 15;
    int b     = bid >> 7;
    int ti    = seg >> 2;
    int tj    = seg & 3;
    int r0    = strip * 16;
    int tid   = threadIdx.x;

    int row = tid >> 5;           // warp 0..17 = smem row (warp-uniform)
    int l   = tid & 31;           // lane = float4 column group
    int gr  = r0 - 1 + row;       // row within tile (-1 .. 128)

    // ---- mbarrier init (one per row), then make visible block-wide ----
    if (tid < 18) mbar_init(smem_u32(&mbar[tid]), 1);
    __syncthreads();

    // ---- Phase 1: channel-L2 into smem (uninterrupted load stream) ----
    float ax = 0.f, ay = 0.f, az = 0.f, aw = 0.f;
    if ((unsigned)gr < (unsigned)TS) {
        const float4* xp = reinterpret_cast<const float4*>(
            x + (size_t)b * CHW + (size_t)(ti * TS + gr) * Ww + tj * TS) + l;
        #pragma unroll 16
        for (int c = 0; c < Cc; ++c) {
            float4 v = __ldg(xp + (size_t)c * (HW / 4));
            ax = fmaf(v.x, v.x, ax);
            ay = fmaf(v.y, v.y, ay);
            az = fmaf(v.z, v.z, az);
            aw = fmaf(v.w, v.w, aw);
        }
    }
    float4 r;
    r.x = sqrtf(ax);
    r.y = sqrtf(ay);
    r.z = sqrtf(az);
    r.w = sqrtf(aw);
    *reinterpret_cast<float4*>(&s[row][l * 4]) = r;    // zeros for out-of-tile halo rows
    __syncwarp();
    if (l == 0) mbar_arrive(smem_u32(&mbar[row]));     // row ready

    // ---- Phase 2: conv + sigmoid; warp w handles output row w (w < 16) ----
    if (row < 16) {
        // Weights + bias (ptxas hoists these LDGs into the load-stall shadow)
        float wt[9];
        const float* wseg = conv_w + seg * 9;
        #pragma unroll
        for (int k = 0; k < 9; ++k) wt[k] = __ldg(wseg + k);
        float bias = __ldg(conv_b + seg);

        // Wait only for the 3 rows this warp consumes
        mbar_wait_p0(smem_u32(&mbar[row]));
        mbar_wait_p0(smem_u32(&mbar[row + 1]));
        mbar_wait_p0(smem_u32(&mbar[row + 2]));

        int cq = l * 4;           // output col of first element

        float a0 = 0.f, a1 = 0.f, a2 = 0.f, a3 = 0.f;
        #pragma unroll
        for (int dr = 0; dr < 3; ++dr) {
            const float* sr = s[row + dr];
            float4 vc = *reinterpret_cast<const float4*>(&sr[cq]);
            float vm1 = (cq == 0)   ? 0.f : sr[cq - 1];
            float vp4 = (cq == 124) ? 0.f : sr[cq + 4];
            float w0 = wt[dr * 3], w1 = wt[dr * 3 + 1], w2 = wt[dr * 3 + 2];
            a0 = fmaf(w0, vm1,  fmaf(w1, vc.x, fmaf(w2, vc.y, a0)));
            a1 = fmaf(w0, vc.x, fmaf(w1, vc.y, fmaf(w2, vc.z, a1)));
            a2 = fmaf(w0, vc.y, fmaf(w1, vc.z, fmaf(w2, vc.w, a2)));
            a3 = fmaf(w0, vc.z, fmaf(w1, vc.w, fmaf(w2, vp4,  a3)));
        }

        float4 o;
        o.x = 1.f / (1.f + __expf(-(a0 + bias)));
        o.y = 1.f / (1.f + __expf(-(a1 + bias)));
        o.z = 1.f / (1.f + __expf(-(a2 + bias)));
        o.w = 1.f / (1.f + __expf(-(a3 + bias)));

        size_t oofs = (size_t)b * HW + (size_t)seg * (TS * TS)
                    + (size_t)(r0 + row) * TS + cq;
        __stwt(reinterpret_cast<float4*>(out + oofs), o);   // streaming store
    }
}

extern "C" void kernel_launch(void* const* d_in, const int* in_sizes, int n_in,
                              void* d_out, int out_size) {
    const float* x  = (const float*)d_in[0];
    const float* cw = (const float*)d_in[1];
    const float* cb = (const float*)d_in[2];
    float* out = (float*)d_out;

    // 8 strips x 16 segs x 8 batches = 1024 blocks, 576 threads each
    fused_kernel<<<Bb * NSEG * 8, 576>>>(x, cw, cb, out);
}